// round 9
// baseline (speedup 1.0000x reference)
#include <cuda_runtime.h>
#include <cuda_fp16.h>
#include <cstdint>
#include <math.h>

#define BATCH  2
#define SEQ    2047
#define NQ     2048
#define CDIM   1024
#define NHEAD  16
#define DHEAD  64
#define QT_TILES 32   // NQ / 64

// ---------------- scratch (device globals: no allocations allowed) ----------
__device__ __half d_xg[(size_t)BATCH * NQ * CDIM];           // fp16 inputs
__device__ __half d_qkvbuf[(size_t)BATCH * NQ * 3 * CDIM];   // fp16 (Q pre-scaled)
__device__ __half d_attbuf[(size_t)BATCH * NQ * CDIM];       // fp16 attention out
__device__ __half d_qkvw_h[(size_t)3 * CDIM * CDIM];         // fp16 weights
__device__ __half d_projw_h[(size_t)CDIM * CDIM];

// ======================= helpers ========================
__device__ __forceinline__ uint32_t smem_u32(const void* p) {
    uint32_t a;
    asm("{ .reg .u64 t; cvta.to.shared.u64 t, %1; cvt.u32.u64 %0, t; }"
        : "=r"(a) : "l"(p));
    return a;
}
__device__ __forceinline__ float ex2(float x) {
    float r;
    asm("ex2.approx.ftz.f32 %0, %1;" : "=f"(r) : "f"(x));
    return r;
}
__device__ __forceinline__ uint32_t packh2(float lo, float hi) {
    __half2 h = __floats2half2_rn(lo, hi);
    return *(uint32_t*)&h;
}
__device__ __forceinline__ void ldsm_x4(uint32_t& r0, uint32_t& r1,
                                        uint32_t& r2, uint32_t& r3, uint32_t addr) {
    asm volatile("ldmatrix.sync.aligned.m8n8.x4.shared.b16 {%0,%1,%2,%3}, [%4];"
                 : "=r"(r0), "=r"(r1), "=r"(r2), "=r"(r3) : "r"(addr));
}
__device__ __forceinline__ void ldsm_x4t(uint32_t& r0, uint32_t& r1,
                                         uint32_t& r2, uint32_t& r3, uint32_t addr) {
    asm volatile("ldmatrix.sync.aligned.m8n8.x4.trans.shared.b16 {%0,%1,%2,%3}, [%4];"
                 : "=r"(r0), "=r"(r1), "=r"(r2), "=r"(r3) : "r"(addr));
}
__device__ __forceinline__ void mma_f16(float* c, const uint32_t* a,
                                        uint32_t b0, uint32_t b1) {
    asm volatile(
        "mma.sync.aligned.m16n8k16.row.col.f32.f16.f16.f32 "
        "{%0,%1,%2,%3}, {%4,%5,%6,%7}, {%8,%9}, {%0,%1,%2,%3};"
        : "+f"(c[0]), "+f"(c[1]), "+f"(c[2]), "+f"(c[3])
        : "r"(a[0]), "r"(a[1]), "r"(a[2]), "r"(a[3]), "r"(b0), "r"(b1));
}
#define CP_ASYNC16(dst, src) \
    asm volatile("cp.async.cg.shared.global [%0], [%1], 16;" \
                 :: "r"(dst), "l"(src) : "memory")
#define CP_COMMIT()  asm volatile("cp.async.commit_group;" ::: "memory")
#define CP_WAIT1()   asm volatile("cp.async.wait_group 1;" ::: "memory")
#define CP_WAIT0()   asm volatile("cp.async.wait_group 0;" ::: "memory")

__device__ __forceinline__ uint32_t swz(uint32_t off) {    // 128B-row tiles
    return off ^ ((off >> 3) & 0x70);
}

// ---------------- kernel: fp32 -> fp16 weight conversion --------------------
__global__ void bwa_w2h(const float* __restrict__ src, __half* __restrict__ dst,
                        int n4, int qrows4, float qsc)
{
    int i = blockIdx.x * blockDim.x + threadIdx.x;
    if (i >= n4) return;
    float4 v = ((const float4*)src)[i];
    float s = (i < qrows4) ? qsc : 1.0f;
    ((__half2*)dst)[i * 2 + 0] = __floats2half2_rn(v.x * s, v.y * s);
    ((__half2*)dst)[i * 2 + 1] = __floats2half2_rn(v.z * s, v.w * s);
}

// ---------------- kernel 0: build xg = concat(g, x) as fp16 -----------------
__global__ void bwa_build_xg(const float* __restrict__ x,
                             const float* __restrict__ g)
{
    int i4 = blockIdx.x * blockDim.x + threadIdx.x;
    const int total = BATCH * NQ * (CDIM / 4);
    if (i4 >= total) return;
    int c4  = i4 & 255;
    int row = i4 >> 8;
    int n   = row & (NQ - 1);
    int b   = row >> 11;
    float4 v;
    if (n == 0) v = ((const float4*)g)[c4];
    else        v = ((const float4*)x)[((size_t)(b * SEQ + n - 1)) * 256 + c4];
    ((__half2*)d_xg)[i4 * 2 + 0] = __floats2half2_rn(v.x, v.y);
    ((__half2*)d_xg)[i4 * 2 + 1] = __floats2half2_rn(v.z, v.w);
}

// ============ fp16 mma.sync GEMM: C = A @ W^T (+bias/epilogue) ==============
// CTA tile 128x128, 4 warps (2m x 2n), warp tile 64x64 -> 8 ldsm per 32 mma.
// K chunks of 64, 3-stage cp.async pipeline.
#define GSTAGES 3
#define GSTAGE_BYTES 32768                          // A 16KB + B 16KB
#define GEMM_SMEM_TOTAL (GSTAGES * GSTAGE_BYTES)    // 96 KB

template<int EPI>
__global__ void __launch_bounds__(128, 2)
bwa_mma_gemm(const __half* __restrict__ A, const __half* __restrict__ W,
             void* __restrict__ Cv, int Nn, int K,
             const float* __restrict__ bias)
{
    extern __shared__ __align__(1024) char smem[];
    const uint32_t sb = smem_u32(smem);
    const int tid  = threadIdx.x;
    const int wid  = tid >> 5;
    const int lane = tid & 31;
    const int wm   = wid >> 1;       // 0..1 -> m offset 64*wm
    const int wn   = wid & 1;        // 0..1 -> n offset 64*wn
    const int m0   = blockIdx.y * 128;
    const int n0   = blockIdx.x * 128;

    const __half* Abase = A + (size_t)m0 * K;
    const __half* Wbase = W + (size_t)n0 * K;

    // per stage: A tile 128x64 halfs = 1024 x 16B, 8 per thread; B same
    uint32_t dstoff[8];
    const __half* srcA[8];
    const __half* srcW[8];
    #pragma unroll
    for (int j = 0; j < 8; j++) {
        int i   = tid + 128 * j;
        int row = i >> 3;
        int c   = i & 7;
        dstoff[j] = swz((uint32_t)(row * 128 + c * 16));
        srcA[j] = Abase + (size_t)row * K + c * 8;
        srcW[j] = Wbase + (size_t)row * K + c * 8;
    }

    const int nch = K >> 6;          // K/64 = 16
    #pragma unroll
    for (int pc = 0; pc < 2; pc++) {
        uint32_t sA = sb + pc * GSTAGE_BYTES;
        uint32_t sB = sA + 16384;
        #pragma unroll
        for (int j = 0; j < 8; j++) {
            CP_ASYNC16(sA + dstoff[j], srcA[j] + pc * 64);
            CP_ASYNC16(sB + dstoff[j], srcW[j] + pc * 64);
        }
        CP_COMMIT();
    }

    float acc[4][8][4];
    #pragma unroll
    for (int mt = 0; mt < 4; mt++)
        #pragma unroll
        for (int j = 0; j < 8; j++)
            #pragma unroll
            for (int q = 0; q < 4; q++) acc[mt][j][q] = 0.f;

    const uint32_t lr = (uint32_t)(lane & 15);
    const uint32_t lc = (uint32_t)((lane >> 4) << 4);

    for (int kc = 0; kc < nch; kc++) {
        CP_WAIT1();
        __syncthreads();

        const uint32_t sA = sb + (kc % GSTAGES) * GSTAGE_BYTES;
        const uint32_t sB = sA + 16384;

        #pragma unroll
        for (int ks = 0; ks < 4; ks++) {           // 4 x k16 per chunk
            const uint32_t cb = (uint32_t)(ks * 32) + lc;
            uint32_t a[4][4];
            #pragma unroll
            for (int mt = 0; mt < 4; mt++) {
                uint32_t row = (uint32_t)(wm * 64 + mt * 16) + lr;
                ldsm_x4(a[mt][0], a[mt][1], a[mt][2], a[mt][3],
                        sA + swz(row * 128 + cb));
            }
            uint32_t br[4][4];
            #pragma unroll
            for (int bt = 0; bt < 4; bt++) {
                uint32_t row = (uint32_t)(wn * 64 + bt * 16) + lr;
                ldsm_x4(br[bt][0], br[bt][1], br[bt][2], br[bt][3],
                        sB + swz(row * 128 + cb));
            }
            #pragma unroll
            for (int mt = 0; mt < 4; mt++)
                #pragma unroll
                for (int j = 0; j < 8; j++)
                    mma_f16(acc[mt][j], a[mt],
                            br[j >> 1][j & 1], br[j >> 1][2 + (j & 1)]);
        }

        if (kc + 2 < nch) {
            uint32_t fA = sb + ((kc + 2) % GSTAGES) * GSTAGE_BYTES;
            uint32_t fB = fA + 16384;
            #pragma unroll
            for (int j = 0; j < 8; j++) {
                CP_ASYNC16(fA + dstoff[j], srcA[j] + (kc + 2) * 64);
                CP_ASYNC16(fB + dstoff[j], srcW[j] + (kc + 2) * 64);
            }
        }
        CP_COMMIT();
    }

    const int lrow4 = lane >> 2;
    const int lcol2 = (lane & 3) * 2;
    #pragma unroll
    for (int mt = 0; mt < 4; mt++) {
        const int rbase = m0 + wm * 64 + mt * 16 + lrow4;
        #pragma unroll
        for (int j = 0; j < 8; j++) {
            const int col = n0 + wn * 64 + j * 8 + lcol2;
            if (EPI == 0) {
                __half* Ch = (__half*)Cv;
                *(__half2*)(Ch + (size_t)rbase * Nn + col) =
                    __floats2half2_rn(acc[mt][j][0], acc[mt][j][1]);
                *(__half2*)(Ch + (size_t)(rbase + 8) * Nn + col) =
                    __floats2half2_rn(acc[mt][j][2], acc[mt][j][3]);
            } else {
                float* C = (float*)Cv;
                float2 bb = *(const float2*)(bias + col);
                int n0r = rbase & (NQ - 1), b0r = rbase >> 11;
                if (n0r > 0) {
                    float* p = C + (size_t)(b0r * SEQ + n0r - 1) * Nn + col;
                    *(float2*)p = make_float2(acc[mt][j][0] + bb.x,
                                              acc[mt][j][1] + bb.y);
                }
                int r1 = rbase + 8;
                int n1r = r1 & (NQ - 1), b1r = r1 >> 11;
                if (n1r > 0) {
                    float* p = C + (size_t)(b1r * SEQ + n1r - 1) * Nn + col;
                    *(float2*)p = make_float2(acc[mt][j][2] + bb.x,
                                              acc[mt][j][3] + bb.y);
                }
            }
        }
    }
}

// ============ block-causal flash attention, fp16 mma (R7 version) ===========
// CTA = (b, h, qt): 64 queries, 4 warps (16 rows each). Q fragments preloaded;
// K/V double-buffered cp.async; P stays in registers; V via ldmatrix.trans.
// smem: Q 8KB + 2 stages x (K 8KB + V 8KB) = 40 KB.
#define ATT_SMEM_TOTAL 40960

__global__ void __launch_bounds__(128, 4)
bwa_attn_mma(const __half* __restrict__ qkv, __half* __restrict__ att)
{
    extern __shared__ __align__(1024) char smem[];
    const uint32_t sb = smem_u32(smem);
    const uint32_t Qs = sb;

    const int tid  = threadIdx.x;
    const int w    = tid >> 5;
    const int lane = tid & 31;
    const int qt   = (QT_TILES - 1) - (int)blockIdx.x;  // big tiles first
    const int h    = blockIdx.y;
    const int b    = blockIdx.z;

    const long long base = (long long)b * NQ * 3 * CDIM;
    const __half* qp = qkv + base + h * DHEAD;
    const __half* kp = qkv + base + CDIM + h * DHEAD;
    const __half* vp = qkv + base + 2 * CDIM + h * DHEAD;

    const int crow[4] = { tid >> 3, (tid + 128) >> 3, (tid + 256) >> 3, (tid + 384) >> 3 };
    const int ccol    = (tid & 7) * 8;
    uint32_t  coff[4];
    #pragma unroll
    for (int j = 0; j < 4; j++)
        coff[j] = swz((uint32_t)(crow[j] * 128 + (tid & 7) * 16));

    #pragma unroll
    for (int j = 0; j < 4; j++)
        CP_ASYNC16(Qs + coff[j], qp + (long long)(qt * 64 + crow[j]) * (3 * CDIM) + ccol);
    CP_COMMIT();

    {
        uint32_t Ks = sb + 8192, Vs = sb + 16384;
        #pragma unroll
        for (int j = 0; j < 4; j++) {
            CP_ASYNC16(Ks + coff[j], kp + (long long)crow[j] * (3 * CDIM) + ccol);
            CP_ASYNC16(Vs + coff[j], vp + (long long)crow[j] * (3 * CDIM) + ccol);
        }
        CP_COMMIT();
    }

    float o[8][4];
    #pragma unroll
    for (int nt = 0; nt < 8; nt++)
        #pragma unroll
        for (int q = 0; q < 4; q++) o[nt][q] = 0.f;
    float mrow[2] = { -1e30f, -1e30f };
    float lsum[2] = { 0.f, 0.f };

    const uint32_t lr = (uint32_t)(lane & 15);
    const uint32_t lc = (uint32_t)((lane >> 4) << 4);
    uint32_t qf[4][4];

    for (int kt = 0; kt <= qt; kt++) {
        if (kt < qt) {
            uint32_t Ks = sb + 8192 + ((kt + 1) & 1) * 16384;
            uint32_t Vs = Ks + 8192;
            #pragma unroll
            for (int j = 0; j < 4; j++) {
                CP_ASYNC16(Ks + coff[j],
                           kp + (long long)((kt + 1) * 64 + crow[j]) * (3 * CDIM) + ccol);
                CP_ASYNC16(Vs + coff[j],
                           vp + (long long)((kt + 1) * 64 + crow[j]) * (3 * CDIM) + ccol);
            }
            CP_COMMIT();
            CP_WAIT1();
        } else {
            CP_WAIT0();
        }
        __syncthreads();

        if (kt == 0) {
            #pragma unroll
            for (int ks = 0; ks < 4; ks++)
                ldsm_x4(qf[ks][0], qf[ks][1], qf[ks][2], qf[ks][3],
                        Qs + swz(((uint32_t)(16 * w) + lr) * 128 + (uint32_t)(32 * ks) + lc));
        }

        const uint32_t Ks = sb + 8192 + (kt & 1) * 16384;
        const uint32_t Vs = Ks + 8192;

        float s[8][4];
        #pragma unroll
        for (int nt = 0; nt < 8; nt++)
            #pragma unroll
            for (int q = 0; q < 4; q++) s[nt][q] = 0.f;

        #pragma unroll
        for (int ks = 0; ks < 4; ks++) {
            const uint32_t cb = (uint32_t)(32 * ks) + lc;
            uint32_t br[4][4];
            #pragma unroll
            for (int bt = 0; bt < 4; bt++)
                ldsm_x4(br[bt][0], br[bt][1], br[bt][2], br[bt][3],
                        Ks + swz(((uint32_t)(16 * bt) + lr) * 128 + cb));
            #pragma unroll
            for (int nt = 0; nt < 8; nt++)
                mma_f16(s[nt], qf[ks], br[nt >> 1][nt & 1], br[nt >> 1][2 + (nt & 1)]);
        }

        float rm0 = -1e30f, rm1 = -1e30f;
        #pragma unroll
        for (int nt = 0; nt < 8; nt++) {
            rm0 = fmaxf(rm0, fmaxf(s[nt][0], s[nt][1]));
            rm1 = fmaxf(rm1, fmaxf(s[nt][2], s[nt][3]));
        }
        rm0 = fmaxf(rm0, __shfl_xor_sync(0xffffffffu, rm0, 1));
        rm0 = fmaxf(rm0, __shfl_xor_sync(0xffffffffu, rm0, 2));
        rm1 = fmaxf(rm1, __shfl_xor_sync(0xffffffffu, rm1, 1));
        rm1 = fmaxf(rm1, __shfl_xor_sync(0xffffffffu, rm1, 2));

        float mn0 = fmaxf(mrow[0], rm0), mn1 = fmaxf(mrow[1], rm1);
        float al0 = ex2(mrow[0] - mn0),  al1 = ex2(mrow[1] - mn1);
        mrow[0] = mn0; mrow[1] = mn1;

        float rs0 = 0.f, rs1 = 0.f;
        #pragma unroll
        for (int nt = 0; nt < 8; nt++) {
            s[nt][0] = ex2(s[nt][0] - mn0);
            s[nt][1] = ex2(s[nt][1] - mn0);
            s[nt][2] = ex2(s[nt][2] - mn1);
            s[nt][3] = ex2(s[nt][3] - mn1);
            rs0 += s[nt][0] + s[nt][1];
            rs1 += s[nt][2] + s[nt][3];
        }
        rs0 += __shfl_xor_sync(0xffffffffu, rs0, 1);
        rs0 += __shfl_xor_sync(0xffffffffu, rs0, 2);
        rs1 += __shfl_xor_sync(0xffffffffu, rs1, 1);
        rs1 += __shfl_xor_sync(0xffffffffu, rs1, 2);
        lsum[0] = lsum[0] * al0 + rs0;
        lsum[1] = lsum[1] * al1 + rs1;
        #pragma unroll
        for (int nt = 0; nt < 8; nt++) {
            o[nt][0] *= al0; o[nt][1] *= al0;
            o[nt][2] *= al1; o[nt][3] *= al1;
        }

        uint32_t pa[4][4];
        #pragma unroll
        for (int j = 0; j < 4; j++) {
            pa[j][0] = packh2(s[2 * j][0],     s[2 * j][1]);
            pa[j][1] = packh2(s[2 * j][2],     s[2 * j][3]);
            pa[j][2] = packh2(s[2 * j + 1][0], s[2 * j + 1][1]);
            pa[j][3] = packh2(s[2 * j + 1][2], s[2 * j + 1][3]);
        }

        #pragma unroll
        for (int j = 0; j < 4; j++) {
            uint32_t bv[4][4];
            #pragma unroll
            for (int dt = 0; dt < 4; dt++)
                ldsm_x4t(bv[dt][0], bv[dt][1], bv[dt][2], bv[dt][3],
                         Vs + swz(((uint32_t)(16 * j) + lr) * 128
                                  + (uint32_t)(32 * dt) + lc));
            #pragma unroll
            for (int nt = 0; nt < 8; nt++)
                mma_f16(o[nt], pa[j],
                        bv[nt >> 1][(nt & 1) * 2], bv[nt >> 1][(nt & 1) * 2 + 1]);
        }
        __syncthreads();
    }

    float i0 = 1.f / lsum[0], i1 = 1.f / lsum[1];
    int r0 = qt * 64 + 16 * w + (lane >> 2);
    __half* orow0 = att + ((long long)b * NQ + r0) * CDIM + h * DHEAD;
    __half* orow1 = orow0 + 8 * CDIM;
    #pragma unroll
    for (int nt = 0; nt < 8; nt++) {
        int col = 8 * nt + 2 * (lane & 3);
        *(__half2*)(orow0 + col) = __floats2half2_rn(o[nt][0] * i0, o[nt][1] * i0);
        *(__half2*)(orow1 + col) = __floats2half2_rn(o[nt][2] * i1, o[nt][3] * i1);
    }
}

// ---------------- launch ----------------------------------------------------
extern "C" void kernel_launch(void* const* d_in, const int* in_sizes, int n_in,
                              void* d_out, int out_size)
{
    const float* x      = (const float*)d_in[0];
    const float* g      = (const float*)d_in[1];
    const float* qkv_w  = (const float*)d_in[2];
    const float* proj_w = (const float*)d_in[3];
    const float* proj_b = (const float*)d_in[4];
    float* out = (float*)d_out;

    __half *xg, *qkvbuf, *attbuf, *qkvw_h, *projw_h;
    cudaGetSymbolAddress((void**)&xg,      d_xg);
    cudaGetSymbolAddress((void**)&qkvbuf,  d_qkvbuf);
    cudaGetSymbolAddress((void**)&attbuf,  d_attbuf);
    cudaGetSymbolAddress((void**)&qkvw_h,  d_qkvw_h);
    cudaGetSymbolAddress((void**)&projw_h, d_projw_h);

    cudaFuncSetAttribute(bwa_mma_gemm<0>,
                         cudaFuncAttributeMaxDynamicSharedMemorySize, GEMM_SMEM_TOTAL);
    cudaFuncSetAttribute(bwa_mma_gemm<1>,
                         cudaFuncAttributeMaxDynamicSharedMemorySize, GEMM_SMEM_TOTAL);
    cudaFuncSetAttribute(bwa_attn_mma,
                         cudaFuncAttributeMaxDynamicSharedMemorySize, ATT_SMEM_TOTAL);

    const float QSC = 0.125f * 1.44269504f;   // softmax scale * log2(e)

    // 0) convert weights to fp16 (Q weight rows pre-scaled)
    {
        int n4 = 3 * CDIM * CDIM / 4;
        int qrows4 = CDIM * CDIM / 4;          // first 1024 rows = Wq
        bwa_w2h<<<(n4 + 255) / 256, 256>>>(qkv_w, qkvw_h, n4, qrows4, QSC);
        n4 = CDIM * CDIM / 4;
        bwa_w2h<<<(n4 + 255) / 256, 256>>>(proj_w, projw_h, n4, 0, 1.0f);
    }
    // 1) concat global token + x (fp16)
    {
        int total4 = BATCH * NQ * (CDIM / 4);
        bwa_build_xg<<<(total4 + 255) / 256, 256>>>(x, g);
    }
    // 2) QKV GEMM (fp16 mma, warp tile 64x64)
    {
        dim3 grid(3 * CDIM / 128, (BATCH * NQ) / 128, 1);
        bwa_mma_gemm<0><<<grid, 128, GEMM_SMEM_TOTAL>>>(
            xg, qkvw_h, qkvbuf, 3 * CDIM, CDIM, nullptr);
    }
    // 3) block-causal flash attention (fp16, 64-query CTAs — R7 version)
    {
        dim3 grid(QT_TILES, NHEAD, BATCH);
        bwa_attn_mma<<<grid, 128, ATT_SMEM_TOTAL>>>(qkvbuf, attbuf);
    }
    // 4) output projection with fused concat-drop + bias (fp32 store)
    {
        dim3 grid(CDIM / 128, (BATCH * NQ) / 128, 1);
        bwa_mma_gemm<1><<<grid, 128, GEMM_SMEM_TOTAL>>>(
            attbuf, projw_h, out, CDIM, CDIM, proj_b);
    }
}

// round 11
// speedup vs baseline: 1.0524x; 1.0524x over previous
#include <cuda_runtime.h>
#include <cuda_fp16.h>
#include <cstdint>
#include <math.h>

#define BATCH  2
#define SEQ    2047
#define NQ     2048
#define CDIM   1024
#define NHEAD  16
#define DHEAD  64
#define QT_TILES 32   // NQ / 64

// ---------------- scratch (device globals: no allocations allowed) ----------
__device__ __half d_xg[(size_t)BATCH * NQ * CDIM];           // fp16 inputs
__device__ __half d_qkvbuf[(size_t)BATCH * NQ * 3 * CDIM];   // fp16 (Q pre-scaled)
__device__ __half d_attbuf[(size_t)BATCH * NQ * CDIM];       // fp16 attention out
__device__ __half d_qkvw_h[(size_t)3 * CDIM * CDIM];         // fp16 weights
__device__ __half d_projw_h[(size_t)CDIM * CDIM];

// ======================= helpers ========================
__device__ __forceinline__ uint32_t smem_u32(const void* p) {
    uint32_t a;
    asm("{ .reg .u64 t; cvta.to.shared.u64 t, %1; cvt.u32.u64 %0, t; }"
        : "=r"(a) : "l"(p));
    return a;
}
__device__ __forceinline__ float ex2(float x) {
    float r;
    asm("ex2.approx.ftz.f32 %0, %1;" : "=f"(r) : "f"(x));
    return r;
}
__device__ __forceinline__ uint32_t packh2(float lo, float hi) {
    __half2 h = __floats2half2_rn(lo, hi);
    return *(uint32_t*)&h;
}
__device__ __forceinline__ void ldsm_x4(uint32_t& r0, uint32_t& r1,
                                        uint32_t& r2, uint32_t& r3, uint32_t addr) {
    asm volatile("ldmatrix.sync.aligned.m8n8.x4.shared.b16 {%0,%1,%2,%3}, [%4];"
                 : "=r"(r0), "=r"(r1), "=r"(r2), "=r"(r3) : "r"(addr));
}
__device__ __forceinline__ void ldsm_x4t(uint32_t& r0, uint32_t& r1,
                                         uint32_t& r2, uint32_t& r3, uint32_t addr) {
    asm volatile("ldmatrix.sync.aligned.m8n8.x4.trans.shared.b16 {%0,%1,%2,%3}, [%4];"
                 : "=r"(r0), "=r"(r1), "=r"(r2), "=r"(r3) : "r"(addr));
}
__device__ __forceinline__ void mma_f16(float* c, const uint32_t* a,
                                        uint32_t b0, uint32_t b1) {
    asm volatile(
        "mma.sync.aligned.m16n8k16.row.col.f32.f16.f16.f32 "
        "{%0,%1,%2,%3}, {%4,%5,%6,%7}, {%8,%9}, {%0,%1,%2,%3};"
        : "+f"(c[0]), "+f"(c[1]), "+f"(c[2]), "+f"(c[3])
        : "r"(a[0]), "r"(a[1]), "r"(a[2]), "r"(a[3]), "r"(b0), "r"(b1));
}
#define CP_ASYNC16(dst, src) \
    asm volatile("cp.async.cg.shared.global [%0], [%1], 16;" \
                 :: "r"(dst), "l"(src) : "memory")
#define CP_COMMIT()  asm volatile("cp.async.commit_group;" ::: "memory")
#define CP_WAIT1()   asm volatile("cp.async.wait_group 1;" ::: "memory")
#define CP_WAIT0()   asm volatile("cp.async.wait_group 0;" ::: "memory")

__device__ __forceinline__ uint32_t swz(uint32_t off) {    // 128B-row tiles
    return off ^ ((off >> 3) & 0x70);
}

// ---------------- fused prep: weights->fp16 (+Q scale fold) and xg ----------
// One launch covers: qkv_w (786432 f4), proj_w (262144 f4), xg (1048576 f4).
#define PREP_N0 (3 * CDIM * CDIM / 4)
#define PREP_N1 (CDIM * CDIM / 4)
#define PREP_N2 (BATCH * NQ * (CDIM / 4))
#define PREP_TOTAL (PREP_N0 + PREP_N1 + PREP_N2)

__global__ void bwa_prep(const float* __restrict__ x, const float* __restrict__ g,
                         const float* __restrict__ qkv_w,
                         const float* __restrict__ proj_w)
{
    const float QSC = 0.125f * 1.44269504f;   // softmax scale * log2(e)
    int i = blockIdx.x * blockDim.x + threadIdx.x;
    if (i >= PREP_TOTAL) return;
    if (i < PREP_N0) {
        float4 v = ((const float4*)qkv_w)[i];
        float s = (i < PREP_N1) ? QSC : 1.0f;   // first CDIM rows = Wq
        ((__half2*)d_qkvw_h)[i * 2 + 0] = __floats2half2_rn(v.x * s, v.y * s);
        ((__half2*)d_qkvw_h)[i * 2 + 1] = __floats2half2_rn(v.z * s, v.w * s);
    } else if (i < PREP_N0 + PREP_N1) {
        int j = i - PREP_N0;
        float4 v = ((const float4*)proj_w)[j];
        ((__half2*)d_projw_h)[j * 2 + 0] = __floats2half2_rn(v.x, v.y);
        ((__half2*)d_projw_h)[j * 2 + 1] = __floats2half2_rn(v.z, v.w);
    } else {
        int j = i - PREP_N0 - PREP_N1;
        int c4  = j & 255;
        int row = j >> 8;
        int n   = row & (NQ - 1);
        int b   = row >> 11;
        float4 v;
        if (n == 0) v = ((const float4*)g)[c4];
        else        v = ((const float4*)x)[((size_t)(b * SEQ + n - 1)) * 256 + c4];
        ((__half2*)d_xg)[j * 2 + 0] = __floats2half2_rn(v.x, v.y);
        ((__half2*)d_xg)[j * 2 + 1] = __floats2half2_rn(v.z, v.w);
    }
}

// ============ fp16 mma.sync GEMM: C = A @ W^T (+bias/epilogue) ==============
// R7 config: 256 threads, 8 warps (4m x 2n), warp tile 32x64, K chunks of 64,
// 3-stage cp.async; fill for chunk kc+2 issued BEFORE compute of chunk kc
// (stage is free: top-of-loop barrier proves all warps passed compute kc-1).
#define GSTAGES 3
#define GSTAGE_BYTES 32768
#define GEMM_SMEM_TOTAL (GSTAGES * GSTAGE_BYTES)    // 96 KB

template<int EPI>
__global__ void __launch_bounds__(256)
bwa_mma_gemm(const __half* __restrict__ A, const __half* __restrict__ W,
             void* __restrict__ Cv, int Nn, int K,
             const float* __restrict__ bias)
{
    extern __shared__ __align__(1024) char smem[];
    const uint32_t sb = smem_u32(smem);
    const int tid  = threadIdx.x;
    const int wid  = tid >> 5;
    const int lane = tid & 31;
    const int wm   = wid >> 1;
    const int wn   = wid & 1;
    const int m0   = blockIdx.y * 128;
    const int n0   = blockIdx.x * 128;

    const __half* Abase = A + (size_t)m0 * K;
    const __half* Wbase = W + (size_t)n0 * K;

    uint32_t dstoff[4];
    const __half* srcA[4];
    const __half* srcW[4];
    #pragma unroll
    for (int j = 0; j < 4; j++) {
        int i   = tid + 256 * j;
        int row = i >> 3;
        int c   = i & 7;
        dstoff[j] = swz((uint32_t)(row * 128 + c * 16));
        srcA[j] = Abase + (size_t)row * K + c * 8;
        srcW[j] = Wbase + (size_t)row * K + c * 8;
    }

    const int nch = K >> 6;          // K/64 = 16
    #pragma unroll
    for (int pc = 0; pc < 2; pc++) {
        uint32_t sA = sb + pc * GSTAGE_BYTES;
        uint32_t sB = sA + 16384;
        #pragma unroll
        for (int j = 0; j < 4; j++) {
            CP_ASYNC16(sA + dstoff[j], srcA[j] + pc * 64);
            CP_ASYNC16(sB + dstoff[j], srcW[j] + pc * 64);
        }
        CP_COMMIT();
    }

    float acc[2][8][4];
    #pragma unroll
    for (int mt = 0; mt < 2; mt++)
        #pragma unroll
        for (int j = 0; j < 8; j++)
            #pragma unroll
            for (int q = 0; q < 4; q++) acc[mt][j][q] = 0.f;

    const uint32_t lr = (uint32_t)(lane & 15);
    const uint32_t lc = (uint32_t)((lane >> 4) << 4);

    for (int kc = 0; kc < nch; kc++) {
        CP_WAIT1();
        __syncthreads();

        // fill chunk kc+2 now (stage of chunk kc-1, freed by the barrier above)
        if (kc + 2 < nch) {
            uint32_t fA = sb + ((kc + 2) % GSTAGES) * GSTAGE_BYTES;
            uint32_t fB = fA + 16384;
            #pragma unroll
            for (int j = 0; j < 4; j++) {
                CP_ASYNC16(fA + dstoff[j], srcA[j] + (kc + 2) * 64);
                CP_ASYNC16(fB + dstoff[j], srcW[j] + (kc + 2) * 64);
            }
        }
        CP_COMMIT();

        const uint32_t sA = sb + (kc % GSTAGES) * GSTAGE_BYTES;
        const uint32_t sB = sA + 16384;

        #pragma unroll
        for (int ks = 0; ks < 4; ks++) {
            const uint32_t cb = (uint32_t)(ks * 32) + lc;
            uint32_t a[2][4];
            #pragma unroll
            for (int mt = 0; mt < 2; mt++) {
                uint32_t row = (uint32_t)(wm * 32 + mt * 16) + lr;
                ldsm_x4(a[mt][0], a[mt][1], a[mt][2], a[mt][3],
                        sA + swz(row * 128 + cb));
            }
            uint32_t br[4][4];
            #pragma unroll
            for (int bt = 0; bt < 4; bt++) {
                uint32_t row = (uint32_t)(wn * 64 + bt * 16) + lr;
                ldsm_x4(br[bt][0], br[bt][1], br[bt][2], br[bt][3],
                        sB + swz(row * 128 + cb));
            }
            #pragma unroll
            for (int mt = 0; mt < 2; mt++)
                #pragma unroll
                for (int j = 0; j < 8; j++)
                    mma_f16(acc[mt][j], a[mt],
                            br[j >> 1][j & 1], br[j >> 1][2 + (j & 1)]);
        }
    }

    const int lrow4 = lane >> 2;
    const int lcol2 = (lane & 3) * 2;
    #pragma unroll
    for (int mt = 0; mt < 2; mt++) {
        const int rbase = m0 + wm * 32 + mt * 16 + lrow4;
        #pragma unroll
        for (int j = 0; j < 8; j++) {
            const int col = n0 + wn * 64 + j * 8 + lcol2;
            if (EPI == 0) {
                __half* Ch = (__half*)Cv;
                *(__half2*)(Ch + (size_t)rbase * Nn + col) =
                    __floats2half2_rn(acc[mt][j][0], acc[mt][j][1]);
                *(__half2*)(Ch + (size_t)(rbase + 8) * Nn + col) =
                    __floats2half2_rn(acc[mt][j][2], acc[mt][j][3]);
            } else {
                float* C = (float*)Cv;
                float2 bb = *(const float2*)(bias + col);
                int n0r = rbase & (NQ - 1), b0r = rbase >> 11;
                if (n0r > 0) {
                    float* p = C + (size_t)(b0r * SEQ + n0r - 1) * Nn + col;
                    *(float2*)p = make_float2(acc[mt][j][0] + bb.x,
                                              acc[mt][j][1] + bb.y);
                }
                int r1 = rbase + 8;
                int n1r = r1 & (NQ - 1), b1r = r1 >> 11;
                if (n1r > 0) {
                    float* p = C + (size_t)(b1r * SEQ + n1r - 1) * Nn + col;
                    *(float2*)p = make_float2(acc[mt][j][2] + bb.x,
                                              acc[mt][j][3] + bb.y);
                }
            }
        }
    }
}

// ============ block-causal flash attention, fp16 mma (R7 version) ===========
#define ATT_SMEM_TOTAL 40960

__global__ void __launch_bounds__(128, 4)
bwa_attn_mma(const __half* __restrict__ qkv, __half* __restrict__ att)
{
    extern __shared__ __align__(1024) char smem[];
    const uint32_t sb = smem_u32(smem);
    const uint32_t Qs = sb;

    const int tid  = threadIdx.x;
    const int w    = tid >> 5;
    const int lane = tid & 31;
    const int qt   = (QT_TILES - 1) - (int)blockIdx.x;  // big tiles first
    const int h    = blockIdx.y;
    const int b    = blockIdx.z;

    const long long base = (long long)b * NQ * 3 * CDIM;
    const __half* qp = qkv + base + h * DHEAD;
    const __half* kp = qkv + base + CDIM + h * DHEAD;
    const __half* vp = qkv + base + 2 * CDIM + h * DHEAD;

    const int crow[4] = { tid >> 3, (tid + 128) >> 3, (tid + 256) >> 3, (tid + 384) >> 3 };
    const int ccol    = (tid & 7) * 8;
    uint32_t  coff[4];
    #pragma unroll
    for (int j = 0; j < 4; j++)
        coff[j] = swz((uint32_t)(crow[j] * 128 + (tid & 7) * 16));

    #pragma unroll
    for (int j = 0; j < 4; j++)
        CP_ASYNC16(Qs + coff[j], qp + (long long)(qt * 64 + crow[j]) * (3 * CDIM) + ccol);
    CP_COMMIT();

    {
        uint32_t Ks = sb + 8192, Vs = sb + 16384;
        #pragma unroll
        for (int j = 0; j < 4; j++) {
            CP_ASYNC16(Ks + coff[j], kp + (long long)crow[j] * (3 * CDIM) + ccol);
            CP_ASYNC16(Vs + coff[j], vp + (long long)crow[j] * (3 * CDIM) + ccol);
        }
        CP_COMMIT();
    }

    float o[8][4];
    #pragma unroll
    for (int nt = 0; nt < 8; nt++)
        #pragma unroll
        for (int q = 0; q < 4; q++) o[nt][q] = 0.f;
    float mrow[2] = { -1e30f, -1e30f };
    float lsum[2] = { 0.f, 0.f };

    const uint32_t lr = (uint32_t)(lane & 15);
    const uint32_t lc = (uint32_t)((lane >> 4) << 4);
    uint32_t qf[4][4];

    for (int kt = 0; kt <= qt; kt++) {
        if (kt < qt) {
            uint32_t Ks = sb + 8192 + ((kt + 1) & 1) * 16384;
            uint32_t Vs = Ks + 8192;
            #pragma unroll
            for (int j = 0; j < 4; j++) {
                CP_ASYNC16(Ks + coff[j],
                           kp + (long long)((kt + 1) * 64 + crow[j]) * (3 * CDIM) + ccol);
                CP_ASYNC16(Vs + coff[j],
                           vp + (long long)((kt + 1) * 64 + crow[j]) * (3 * CDIM) + ccol);
            }
            CP_COMMIT();
            CP_WAIT1();
        } else {
            CP_WAIT0();
        }
        __syncthreads();

        if (kt == 0) {
            #pragma unroll
            for (int ks = 0; ks < 4; ks++)
                ldsm_x4(qf[ks][0], qf[ks][1], qf[ks][2], qf[ks][3],
                        Qs + swz(((uint32_t)(16 * w) + lr) * 128 + (uint32_t)(32 * ks) + lc));
        }

        const uint32_t Ks = sb + 8192 + (kt & 1) * 16384;
        const uint32_t Vs = Ks + 8192;

        float s[8][4];
        #pragma unroll
        for (int nt = 0; nt < 8; nt++)
            #pragma unroll
            for (int q = 0; q < 4; q++) s[nt][q] = 0.f;

        #pragma unroll
        for (int ks = 0; ks < 4; ks++) {
            const uint32_t cb = (uint32_t)(32 * ks) + lc;
            uint32_t br[4][4];
            #pragma unroll
            for (int bt = 0; bt < 4; bt++)
                ldsm_x4(br[bt][0], br[bt][1], br[bt][2], br[bt][3],
                        Ks + swz(((uint32_t)(16 * bt) + lr) * 128 + cb));
            #pragma unroll
            for (int nt = 0; nt < 8; nt++)
                mma_f16(s[nt], qf[ks], br[nt >> 1][nt & 1], br[nt >> 1][2 + (nt & 1)]);
        }

        float rm0 = -1e30f, rm1 = -1e30f;
        #pragma unroll
        for (int nt = 0; nt < 8; nt++) {
            rm0 = fmaxf(rm0, fmaxf(s[nt][0], s[nt][1]));
            rm1 = fmaxf(rm1, fmaxf(s[nt][2], s[nt][3]));
        }
        rm0 = fmaxf(rm0, __shfl_xor_sync(0xffffffffu, rm0, 1));
        rm0 = fmaxf(rm0, __shfl_xor_sync(0xffffffffu, rm0, 2));
        rm1 = fmaxf(rm1, __shfl_xor_sync(0xffffffffu, rm1, 1));
        rm1 = fmaxf(rm1, __shfl_xor_sync(0xffffffffu, rm1, 2));

        float mn0 = fmaxf(mrow[0], rm0), mn1 = fmaxf(mrow[1], rm1);
        float al0 = ex2(mrow[0] - mn0),  al1 = ex2(mrow[1] - mn1);
        mrow[0] = mn0; mrow[1] = mn1;

        float rs0 = 0.f, rs1 = 0.f;
        #pragma unroll
        for (int nt = 0; nt < 8; nt++) {
            s[nt][0] = ex2(s[nt][0] - mn0);
            s[nt][1] = ex2(s[nt][1] - mn0);
            s[nt][2] = ex2(s[nt][2] - mn1);
            s[nt][3] = ex2(s[nt][3] - mn1);
            rs0 += s[nt][0] + s[nt][1];
            rs1 += s[nt][2] + s[nt][3];
        }
        rs0 += __shfl_xor_sync(0xffffffffu, rs0, 1);
        rs0 += __shfl_xor_sync(0xffffffffu, rs0, 2);
        rs1 += __shfl_xor_sync(0xffffffffu, rs1, 1);
        rs1 += __shfl_xor_sync(0xffffffffu, rs1, 2);
        lsum[0] = lsum[0] * al0 + rs0;
        lsum[1] = lsum[1] * al1 + rs1;
        #pragma unroll
        for (int nt = 0; nt < 8; nt++) {
            o[nt][0] *= al0; o[nt][1] *= al0;
            o[nt][2] *= al1; o[nt][3] *= al1;
        }

        uint32_t pa[4][4];
        #pragma unroll
        for (int j = 0; j < 4; j++) {
            pa[j][0] = packh2(s[2 * j][0],     s[2 * j][1]);
            pa[j][1] = packh2(s[2 * j][2],     s[2 * j][3]);
            pa[j][2] = packh2(s[2 * j + 1][0], s[2 * j + 1][1]);
            pa[j][3] = packh2(s[2 * j + 1][2], s[2 * j + 1][3]);
        }

        #pragma unroll
        for (int j = 0; j < 4; j++) {
            uint32_t bv[4][4];
            #pragma unroll
            for (int dt = 0; dt < 4; dt++)
                ldsm_x4t(bv[dt][0], bv[dt][1], bv[dt][2], bv[dt][3],
                         Vs + swz(((uint32_t)(16 * j) + lr) * 128
                                  + (uint32_t)(32 * dt) + lc));
            #pragma unroll
            for (int nt = 0; nt < 8; nt++)
                mma_f16(o[nt], pa[j],
                        bv[nt >> 1][(nt & 1) * 2], bv[nt >> 1][(nt & 1) * 2 + 1]);
        }
        __syncthreads();
    }

    float i0 = 1.f / lsum[0], i1 = 1.f / lsum[1];
    int r0 = qt * 64 + 16 * w + (lane >> 2);
    __half* orow0 = att + ((long long)b * NQ + r0) * CDIM + h * DHEAD;
    __half* orow1 = orow0 + 8 * CDIM;
    #pragma unroll
    for (int nt = 0; nt < 8; nt++) {
        int col = 8 * nt + 2 * (lane & 3);
        *(__half2*)(orow0 + col) = __floats2half2_rn(o[nt][0] * i0, o[nt][1] * i0);
        *(__half2*)(orow1 + col) = __floats2half2_rn(o[nt][2] * i1, o[nt][3] * i1);
    }
}

// ---------------- launch ----------------------------------------------------
extern "C" void kernel_launch(void* const* d_in, const int* in_sizes, int n_in,
                              void* d_out, int out_size)
{
    const float* x      = (const float*)d_in[0];
    const float* g      = (const float*)d_in[1];
    const float* qkv_w  = (const float*)d_in[2];
    const float* proj_w = (const float*)d_in[3];
    const float* proj_b = (const float*)d_in[4];
    float* out = (float*)d_out;

    __half *xg, *qkvbuf, *attbuf, *qkvw_h, *projw_h;
    cudaGetSymbolAddress((void**)&xg,      d_xg);
    cudaGetSymbolAddress((void**)&qkvbuf,  d_qkvbuf);
    cudaGetSymbolAddress((void**)&attbuf,  d_attbuf);
    cudaGetSymbolAddress((void**)&qkvw_h,  d_qkvw_h);
    cudaGetSymbolAddress((void**)&projw_h, d_projw_h);

    cudaFuncSetAttribute(bwa_mma_gemm<0>,
                         cudaFuncAttributeMaxDynamicSharedMemorySize, GEMM_SMEM_TOTAL);
    cudaFuncSetAttribute(bwa_mma_gemm<1>,
                         cudaFuncAttributeMaxDynamicSharedMemorySize, GEMM_SMEM_TOTAL);
    cudaFuncSetAttribute(bwa_attn_mma,
                         cudaFuncAttributeMaxDynamicSharedMemorySize, ATT_SMEM_TOTAL);

    // 0) fused prep: weights->fp16 (Q rows pre-scaled) + xg concat->fp16
    bwa_prep<<<(PREP_TOTAL + 255) / 256, 256>>>(x, g, qkv_w, proj_w);

    // 1) QKV GEMM (fp16 mma, R7 config, early-fill pipeline)
    {
        dim3 grid(3 * CDIM / 128, (BATCH * NQ) / 128, 1);
        bwa_mma_gemm<0><<<grid, 256, GEMM_SMEM_TOTAL>>>(
            xg, qkvw_h, qkvbuf, 3 * CDIM, CDIM, nullptr);
    }
    // 2) block-causal flash attention (fp16, R7 version)
    {
        dim3 grid(QT_TILES, NHEAD, BATCH);
        bwa_attn_mma<<<grid, 128, ATT_SMEM_TOTAL>>>(qkvbuf, attbuf);
    }
    // 3) output projection with fused concat-drop + bias (fp32 store)
    {
        dim3 grid(CDIM / 128, (BATCH * NQ) / 128, 1);
        bwa_mma_gemm<1><<<grid, 256, GEMM_SMEM_TOTAL>>>(
            attbuf, projw_h, out, CDIM, CDIM, proj_b);
    }
}